// round 16
// baseline (speedup 1.0000x reference)
#include <cuda_runtime.h>
#include <cuda_bf16.h>
#include <math.h>

#define N_NODES   100000
#define N_EDGES   1600000
#define FEAT      128
#define N_GRAPHS  512
#define N_CLASSES 10

// ---------------- scratch (device globals; referenced ONLY from device code) --
__device__ int   g_deg[N_NODES];
__device__ int   g_off[N_NODES + 1];
__device__ int   g_cur[N_NODES];
__device__ int   g_csr[N_EDGES];
__device__ float g_cnt[N_NODES];
__device__ int   g_end[N_GRAPHS];

__device__ __align__(16) __nv_bfloat16 g_hb[N_NODES * FEAT];    // bf16 shadow (in-place)
__device__ __align__(16) __nv_bfloat16 g_meanb[N_NODES * FEAT]; // bf16 neighbor-mean
__device__ float g_gate[N_NODES];

// ---------------- helpers ----------------
__device__ __forceinline__ void mma_bf16(float* d, const unsigned* a, const unsigned* b) {
    asm volatile(
        "mma.sync.aligned.m16n8k16.row.col.f32.bf16.bf16.f32 "
        "{%0,%1,%2,%3}, {%4,%5,%6,%7}, {%8,%9}, {%0,%1,%2,%3};"
        : "+f"(d[0]), "+f"(d[1]), "+f"(d[2]), "+f"(d[3])
        : "r"(a[0]), "r"(a[1]), "r"(a[2]), "r"(a[3]), "r"(b[0]), "r"(b[1]));
}
__device__ __forceinline__ void bf4_to_f4(uint2 r, float* o) {
    __nv_bfloat162 p0 = *reinterpret_cast<__nv_bfloat162*>(&r.x);
    __nv_bfloat162 p1 = *reinterpret_cast<__nv_bfloat162*>(&r.y);
    float2 f0 = __bfloat1622float2(p0);
    float2 f1 = __bfloat1622float2(p1);
    o[0] = f0.x; o[1] = f0.y; o[2] = f1.x; o[3] = f1.y;
}
__device__ __forceinline__ unsigned bf16pair(float lo, float hi) {
    __nv_bfloat162 p = __float22bfloat162_rn(make_float2(lo, hi));
    return *reinterpret_cast<unsigned*>(&p);
}

// ---------------- setup: zero deg + boundaries + x -> bf16 shadow -------------
__global__ void k_setup(const float* __restrict__ x, const int* __restrict__ batch) {
    int i = blockIdx.x * blockDim.x + threadIdx.x;
    if (i < N_NODES * FEAT / 4) {
        float4 v = __ldg((const float4*)x + i);
        uint2 o;
        o.x = bf16pair(v.x, v.y);
        o.y = bf16pair(v.z, v.w);
        *((uint2*)g_hb + i) = o;
    }
    if (i < N_NODES) {
        g_deg[i] = 0;
        int b  = batch[i];
        int bn = (i + 1 < N_NODES) ? batch[i + 1] : N_GRAPHS;
        if (i == 0)
            for (int g = 0; g < b; g++) g_end[g] = 0;
        for (int g = b; g < bn; g++) g_end[g] = i + 1;
    }
}

// ---------------- CSR build (split layout: src=ei[0..E), dst=ei[E..2E)) ------
__global__ void k_hist(const int* __restrict__ ei) {
    int e2 = blockIdx.x * blockDim.x + threadIdx.x;
    if (e2 < N_EDGES / 2) {
        int2 d = __ldg((const int2*)(ei + N_EDGES) + e2);
        atomicAdd(&g_deg[d.x], 1);
        atomicAdd(&g_deg[d.y], 1);
    }
}

// single-block scan (verified R5-R7): g_deg -> g_off/g_cur/g_cnt
__global__ void k_scan() {
    __shared__ int partial[1024];
    const int T = 1024;
    int t = threadIdx.x;
    int chunk = (N_NODES + T - 1) / T;
    int lo = t * chunk;
    int hi = min(lo + chunk, N_NODES);
    int sum = 0;
    for (int i = lo; i < hi; i++) sum += g_deg[i];
    partial[t] = sum;
    __syncthreads();
    for (int d = 1; d < T; d <<= 1) {
        int v = (t >= d) ? partial[t - d] : 0;
        __syncthreads();
        partial[t] += v;
        __syncthreads();
    }
    int run = (t == 0) ? 0 : partial[t - 1];
    for (int i = lo; i < hi; i++) {
        g_off[i] = run;
        g_cur[i] = run;
        g_cnt[i] = fmaxf((float)g_deg[i], 1.0f);
        run += g_deg[i];
    }
    if (t == T - 1) g_off[N_NODES] = run;
}

__global__ void k_scatter(const int* __restrict__ ei) {
    int e2 = blockIdx.x * blockDim.x + threadIdx.x;
    if (e2 < N_EDGES / 2) {
        int2 d = __ldg((const int2*)(ei + N_EDGES) + e2);
        int2 s = __ldg((const int2*)ei + e2);
        int p0 = atomicAdd(&g_cur[d.x], 1);
        g_csr[p0] = s.x;
        int p1 = atomicAdd(&g_cur[d.y], 1);
        g_csr[p1] = s.y;
    }
}

// ---------------- mean aggregation: warp/node, bf16 gather, unroll 8 ---------
__global__ __launch_bounds__(256) void k_agg() {
    int node = (blockIdx.x * blockDim.x + threadIdx.x) >> 5;
    int lane = threadIdx.x & 31;
    if (node >= N_NODES) return;
    int s = g_off[node], e = g_off[node + 1];
    float ax = 0.f, ay = 0.f, az = 0.f, aw = 0.f;
    const uint2* base = (const uint2*)g_hb;
    int i = s;
    for (; i + 8 <= e; i += 8) {
        uint2 r[8];
#pragma unroll
        for (int q = 0; q < 8; q++)
            r[q] = __ldg(base + (size_t)__ldg(&g_csr[i + q]) * (FEAT / 4) + lane);
#pragma unroll
        for (int q = 0; q < 8; q++) {
            float f[4];
            bf4_to_f4(r[q], f);
            ax += f[0]; ay += f[1]; az += f[2]; aw += f[3];
        }
    }
    for (; i < e; i++) {
        uint2 r = __ldg(base + (size_t)__ldg(&g_csr[i]) * (FEAT / 4) + lane);
        float f[4];
        bf4_to_f4(r, f);
        ax += f[0]; ay += f[1]; az += f[2]; aw += f[3];
    }
    float inv = 1.0f / g_cnt[node];
    uint2 o;
    o.x = bf16pair(ax * inv, ay * inv);
    o.y = bf16pair(az * inv, aw * inv);
    *((uint2*)g_meanb + (size_t)node * (FEAT / 4) + lane) = o;
}

// ---------------- tensor-core fused GEMM, bf16 mma m16n8k16 ------------------
// g_hb <- relu(mean@W1 + h@W2 + bias)   (in place; always bf16 out)
#define GBM 128
#define GBK 32
#define APW 20
#define BPW 136
__global__ __launch_bounds__(256) void k_gemm_tc(
    const float* __restrict__ W1, const float* __restrict__ W2,
    const float* __restrict__ bias, int nrows)
{
    __shared__ unsigned As[GBM * APW];   // 10240 B
    __shared__ unsigned Bs[16 * BPW];    //  8704 B

    int row0 = blockIdx.x * GBM;
    int tid  = threadIdx.x;
    int lane = tid & 31;
    int wid  = tid >> 5;
    int wm   = wid & 3;
    int wn   = wid >> 2;

    int am  = tid >> 3;
    int aw2 = (tid & 7) * 2;
    int bn_s  = tid & 127;
    int bhalf = tid >> 7;

    uint2  ar[4];
    float2 wv[8];

    auto load_chunk = [&](int c) {
        int ph = c >> 2, k0 = (c & 3) * GBK;
        const uint2* __restrict__ Ab = ph ? (const uint2*)g_hb : (const uint2*)g_meanb;
        const float* __restrict__ W  = ph ? W2 : W1;
#pragma unroll
        for (int p = 0; p < 4; p++) {
            int grow = row0 + am + p * 32;
            ar[p] = (grow < nrows)
                ? __ldg(Ab + ((size_t)grow * FEAT + k0 + aw2 * 2) / 4)
                : make_uint2(0u, 0u);
        }
#pragma unroll
        for (int p = 0; p < 8; p++) {
            int kp = 2 * p + bhalf;
            wv[p].x = __ldg(&W[(size_t)(k0 + 2 * kp) * FEAT + bn_s]);
            wv[p].y = __ldg(&W[(size_t)(k0 + 2 * kp + 1) * FEAT + bn_s]);
        }
    };

    float d[2][8][4];
#pragma unroll
    for (int mt = 0; mt < 2; mt++)
#pragma unroll
        for (int nt = 0; nt < 8; nt++)
#pragma unroll
            for (int q = 0; q < 4; q++) d[mt][nt][q] = 0.0f;

    load_chunk(0);
    for (int c = 0; c < 8; c++) {
#pragma unroll
        for (int p = 0; p < 4; p++) {
            int row = am + p * 32;
            *(uint2*)&As[row * APW + aw2] = ar[p];
        }
#pragma unroll
        for (int p = 0; p < 8; p++) {
            int kp = 2 * p + bhalf;
            Bs[kp * BPW + bn_s] = bf16pair(wv[p].x, wv[p].y);
        }
        __syncthreads();
        if (c < 7) load_chunk(c + 1);

#pragma unroll
        for (int ks = 0; ks < 2; ks++) {
            unsigned a[2][4], b[8][2];
            int arow = wm * 32 + (lane >> 2);
            int ka   = ks * 8 + (lane & 3);
#pragma unroll
            for (int mt = 0; mt < 2; mt++) {
                int r0 = arow + mt * 16;
                a[mt][0] = As[r0 * APW + ka];
                a[mt][1] = As[(r0 + 8) * APW + ka];
                a[mt][2] = As[r0 * APW + ka + 4];
                a[mt][3] = As[(r0 + 8) * APW + ka + 4];
            }
            int kb  = ks * 8 + (lane & 3);
            int bn0 = wn * 64 + (lane >> 2);
#pragma unroll
            for (int nt = 0; nt < 8; nt++) {
                b[nt][0] = Bs[kb * BPW + bn0 + nt * 8];
                b[nt][1] = Bs[(kb + 4) * BPW + bn0 + nt * 8];
            }
#pragma unroll
            for (int mt = 0; mt < 2; mt++)
#pragma unroll
                for (int nt = 0; nt < 8; nt++)
                    mma_bf16(d[mt][nt], a[mt], b[nt]);
        }
        __syncthreads();
    }

    // ---- epilogue: bias + relu, bf16 ----
    int rbase = row0 + wm * 32 + (lane >> 2);
    int cbase = wn * 64 + (lane & 3) * 2;
#pragma unroll
    for (int nt = 0; nt < 8; nt++) {
        int col = cbase + nt * 8;
        float bv0 = __ldg(&bias[col]);
        float bv1 = __ldg(&bias[col + 1]);
#pragma unroll
        for (int mt = 0; mt < 2; mt++) {
#pragma unroll
            for (int half = 0; half < 2; half++) {
                int r = rbase + mt * 16 + half * 8;
                if (r < nrows) {
                    float ox = fmaxf(d[mt][nt][half * 2 + 0] + bv0, 0.0f);
                    float oy = fmaxf(d[mt][nt][half * 2 + 1] + bv1, 0.0f);
                    *(unsigned*)(g_hb + (size_t)r * FEAT + col) = bf16pair(ox, oy);
                }
            }
        }
    }
}

// ---------------- fused attention pooling + MLP head (1 block / graph) -------
// reads bf16 g_hb
__global__ __launch_bounds__(128) void k_attnpool(
    const float* __restrict__ gate_w, const float* __restrict__ gate_b,
    const float* __restrict__ lin1_w, const float* __restrict__ lin1_b,
    const float* __restrict__ lin2_w, const float* __restrict__ lin2_b,
    float* __restrict__ out)
{
    int g  = blockIdx.x;
    int lo = (g == 0) ? 0 : g_end[g - 1];
    int hi = g_end[g];
    int t = threadIdx.x, warp = t >> 5, lane = t & 31;

    __shared__ float red4[4];
    __shared__ float s_m, s_s;
    __shared__ float sp[FEAT];
    __shared__ float so[FEAT];
    __shared__ float lg[N_CLASSES];

    // ---- pass 1: gate per node + block max ----
    float4 wv = *(const float4*)(gate_w + lane * 4);
    float gb = __ldg(&gate_b[0]);
    float lmax = -1e30f;
    const uint2* hq = (const uint2*)g_hb;
    for (int node = lo + warp; node < hi; node += 4) {
        uint2 r = __ldg(hq + (size_t)node * (FEAT / 4) + lane);
        float f[4];
        bf4_to_f4(r, f);
        float s = f[0] * wv.x + f[1] * wv.y + f[2] * wv.z + f[3] * wv.w;
#pragma unroll
        for (int d = 16; d > 0; d >>= 1) s += __shfl_xor_sync(0xFFFFFFFFu, s, d);
        s += gb;
        if (lane == 0) g_gate[node] = s;
        lmax = fmaxf(lmax, s);
    }
    if (lane == 0) red4[warp] = lmax;
    __syncthreads();
    if (t == 0)
        s_m = fmaxf(fmaxf(red4[0], red4[1]), fmaxf(red4[2], red4[3]));
    __syncthreads();
    float m = s_m;

    // ---- pass 2: exp + sum ----
    float part = 0.0f;
    for (int node = lo + t; node < hi; node += 128) {
        float e = expf(g_gate[node] - m);
        g_gate[node] = e;
        part += e;
    }
#pragma unroll
    for (int d = 16; d > 0; d >>= 1) part += __shfl_xor_sync(0xFFFFFFFFu, part, d);
    if (lane == 0) red4[warp] = part;
    __syncthreads();
    if (t == 0) s_s = red4[0] + red4[1] + red4[2] + red4[3];
    __syncthreads();
    float s = s_s;
    float invs = (s > 0.0f) ? 1.0f / s : 0.0f;

    // ---- pass 3: weighted feature sum (thread t owns feature t) ----
    float acc = 0.0f;
#pragma unroll 4
    for (int node = lo; node < hi; node++)
        acc += g_gate[node] *
               __bfloat162float(g_hb[(size_t)node * FEAT + t]);
    sp[t] = acc * invs;
    __syncthreads();

    // ---- head: relu(lin1) -> lin2 -> log_softmax ----
    float h1 = lin1_b[t];
#pragma unroll 8
    for (int k = 0; k < FEAT; k++)
        h1 = fmaf(sp[k], lin1_w[(size_t)k * FEAT + t], h1);
    so[t] = fmaxf(h1, 0.0f);
    __syncthreads();

    if (t < N_CLASSES) {
        float a = lin2_b[t];
#pragma unroll 8
        for (int k = 0; k < FEAT; k++)
            a = fmaf(so[k], lin2_w[(size_t)k * N_CLASSES + t], a);
        lg[t] = a;
    }
    __syncthreads();

    if (t == 0) {
        float mx = lg[0];
#pragma unroll
        for (int j = 1; j < N_CLASSES; j++) mx = fmaxf(mx, lg[j]);
        float se = 0.0f;
#pragma unroll
        for (int j = 0; j < N_CLASSES; j++) se += expf(lg[j] - mx);
        float l = logf(se);
#pragma unroll
        for (int j = 0; j < N_CLASSES; j++)
            out[(size_t)g * N_CLASSES + j] = lg[j] - mx - l;
    }
}

// ---------------- launch ----------------
extern "C" void kernel_launch(void* const* d_in, const int* in_sizes, int n_in,
                              void* d_out, int out_size) {
    const float* x      = (const float*)d_in[0];
    const int*   ei     = (const int*)  d_in[1];
    const int*   batch  = (const int*)  d_in[2];
    const float* w1l = (const float*)d_in[3];
    const float* b1  = (const float*)d_in[4];
    const float* w1r = (const float*)d_in[5];
    const float* w2l = (const float*)d_in[6];
    const float* b2  = (const float*)d_in[7];
    const float* w2r = (const float*)d_in[8];
    const float* w3l = (const float*)d_in[9];
    const float* b3  = (const float*)d_in[10];
    const float* w3r = (const float*)d_in[11];
    const float* gate_w = (const float*)d_in[12];
    const float* gate_b = (const float*)d_in[13];
    const float* lin1_w = (const float*)d_in[14];
    const float* lin1_b = (const float*)d_in[15];
    const float* lin2_w = (const float*)d_in[16];
    const float* lin2_b = (const float*)d_in[17];
    float* out = (float*)d_out;

    const int TB = 256;

    k_setup<<<(N_NODES * FEAT / 4 + TB - 1) / TB, TB>>>(x, batch);
    k_hist<<<(N_EDGES / 2 + TB - 1) / TB, TB>>>(ei);
    k_scan<<<1, 1024>>>();
    k_scatter<<<(N_EDGES / 2 + TB - 1) / TB, TB>>>(ei);

    int agg_blocks  = (N_NODES * 32 + TB - 1) / TB;
    int gemm_blocks = (N_NODES + GBM - 1) / GBM;

    // layer 1: shadow <- relu(mean(shadow)@w1l + shadow@w1r + b1)
    k_agg<<<agg_blocks, TB>>>();
    k_gemm_tc<<<gemm_blocks, 256>>>(w1l, w1r, b1, N_NODES);
    // layer 2
    k_agg<<<agg_blocks, TB>>>();
    k_gemm_tc<<<gemm_blocks, 256>>>(w2l, w2r, b2, N_NODES);
    // layer 3
    k_agg<<<agg_blocks, TB>>>();
    k_gemm_tc<<<gemm_blocks, 256>>>(w3l, w3r, b3, N_NODES);

    // fused attentional aggregation + head (bf16 h)
    k_attnpool<<<N_GRAPHS, 128>>>(gate_w, gate_b, lin1_w, lin1_b,
                                  lin2_w, lin2_b, out);
}

// round 17
// speedup vs baseline: 1.6831x; 1.6831x over previous
#include <cuda_runtime.h>
#include <cuda_bf16.h>
#include <math.h>

#define N_NODES   100000
#define N_EDGES   1600000
#define FEAT      128
#define N_GRAPHS  512
#define N_CLASSES 10

#define SCAN_ELEMS 512
#define SCAN_NBLK  ((N_NODES + SCAN_ELEMS - 1) / SCAN_ELEMS)   // 196

// ---------------- scratch (device globals; referenced ONLY from device code) --
__device__ int   g_deg[N_NODES];
__device__ int   g_off[N_NODES + 1];
__device__ int   g_cur[N_NODES];
__device__ int   g_csr[N_EDGES];
__device__ float g_cnt[N_NODES];
__device__ int   g_end[N_GRAPHS];
__device__ int   g_bsum[SCAN_NBLK];
__device__ int   g_bpre[SCAN_NBLK];

__device__ __align__(16) __nv_bfloat16 g_hb[N_NODES * FEAT];    // bf16 shadow (in-place)
__device__ __align__(16) __nv_bfloat16 g_meanb[N_NODES * FEAT]; // bf16 neighbor-mean
__device__ float g_gate[N_NODES];

// ---------------- helpers ----------------
__device__ __forceinline__ void mma_bf16(float* d, const unsigned* a, const unsigned* b) {
    asm volatile(
        "mma.sync.aligned.m16n8k16.row.col.f32.bf16.bf16.f32 "
        "{%0,%1,%2,%3}, {%4,%5,%6,%7}, {%8,%9}, {%0,%1,%2,%3};"
        : "+f"(d[0]), "+f"(d[1]), "+f"(d[2]), "+f"(d[3])
        : "r"(a[0]), "r"(a[1]), "r"(a[2]), "r"(a[3]), "r"(b[0]), "r"(b[1]));
}
__device__ __forceinline__ void bf4_to_f4(uint2 r, float* o) {
    __nv_bfloat162 p0 = *reinterpret_cast<__nv_bfloat162*>(&r.x);
    __nv_bfloat162 p1 = *reinterpret_cast<__nv_bfloat162*>(&r.y);
    float2 f0 = __bfloat1622float2(p0);
    float2 f1 = __bfloat1622float2(p1);
    o[0] = f0.x; o[1] = f0.y; o[2] = f1.x; o[3] = f1.y;
}
__device__ __forceinline__ unsigned bf16pair(float lo, float hi) {
    __nv_bfloat162 p = __float22bfloat162_rn(make_float2(lo, hi));
    return *reinterpret_cast<unsigned*>(&p);
}

// ---------------- setup: zero deg + boundaries + x -> bf16 shadow -------------
__global__ void k_setup(const float* __restrict__ x, const int* __restrict__ batch) {
    int i = blockIdx.x * blockDim.x + threadIdx.x;
    if (i < N_NODES * FEAT / 4) {
        float4 v = __ldg((const float4*)x + i);
        uint2 o;
        o.x = bf16pair(v.x, v.y);
        o.y = bf16pair(v.z, v.w);
        *((uint2*)g_hb + i) = o;
    }
    if (i < N_NODES) {
        g_deg[i] = 0;
        int b  = batch[i];
        int bn = (i + 1 < N_NODES) ? batch[i + 1] : N_GRAPHS;
        if (i == 0)
            for (int g = 0; g < b; g++) g_end[g] = 0;
        for (int g = b; g < bn; g++) g_end[g] = i + 1;
    }
}

// ---------------- CSR build (split layout: src=ei[0..E), dst=ei[E..2E)) ------
__global__ void k_hist(const int* __restrict__ ei) {
    int e2 = blockIdx.x * blockDim.x + threadIdx.x;
    if (e2 < N_EDGES / 2) {
        int2 d = __ldg((const int2*)(ei + N_EDGES) + e2);
        atomicAdd(&g_deg[d.x], 1);
        atomicAdd(&g_deg[d.y], 1);
    }
}

// 3-phase parallel exclusive scan (verified R8-R15, ~14us total)
__global__ void k_scan_a() {
    int b = blockIdx.x, t = threadIdx.x;
    int i0 = b * SCAN_ELEMS + t * 2;
    int d0 = (i0 < N_NODES) ? g_deg[i0] : 0;
    int d1 = (i0 + 1 < N_NODES) ? g_deg[i0 + 1] : 0;
    __shared__ int sh[256];
    sh[t] = d0 + d1;
    __syncthreads();
    for (int s = 128; s > 0; s >>= 1) {
        if (t < s) sh[t] += sh[t + s];
        __syncthreads();
    }
    if (t == 0) g_bsum[b] = sh[0];
}
__global__ void k_scan_b() {
    int t = threadIdx.x;
    __shared__ int sh[256];
    int v = (t < SCAN_NBLK) ? g_bsum[t] : 0;
    sh[t] = v;
    __syncthreads();
    for (int d = 1; d < 256; d <<= 1) {
        int x = (t >= d) ? sh[t - d] : 0;
        __syncthreads();
        sh[t] += x;
        __syncthreads();
    }
    if (t < SCAN_NBLK) g_bpre[t] = sh[t] - v;
}
__global__ void k_scan_c() {
    int b = blockIdx.x, t = threadIdx.x;
    int i0 = b * SCAN_ELEMS + t * 2;
    int d0 = (i0 < N_NODES) ? g_deg[i0] : 0;
    int d1 = (i0 + 1 < N_NODES) ? g_deg[i0 + 1] : 0;
    __shared__ int sh[256];
    int v = d0 + d1;
    sh[t] = v;
    __syncthreads();
    for (int d = 1; d < 256; d <<= 1) {
        int x = (t >= d) ? sh[t - d] : 0;
        __syncthreads();
        sh[t] += x;
        __syncthreads();
    }
    int pre = g_bpre[b] + sh[t] - v;
    if (i0 < N_NODES) {
        g_off[i0] = pre; g_cur[i0] = pre;
        g_cnt[i0] = fmaxf((float)d0, 1.0f);
    }
    if (i0 + 1 < N_NODES) {
        g_off[i0 + 1] = pre + d0; g_cur[i0 + 1] = pre + d0;
        g_cnt[i0 + 1] = fmaxf((float)d1, 1.0f);
    }
    if (b == 0 && t == 0) g_off[N_NODES] = N_EDGES;
}

__global__ void k_scatter(const int* __restrict__ ei) {
    int e2 = blockIdx.x * blockDim.x + threadIdx.x;
    if (e2 < N_EDGES / 2) {
        int2 d = __ldg((const int2*)(ei + N_EDGES) + e2);
        int2 s = __ldg((const int2*)ei + e2);
        int p0 = atomicAdd(&g_cur[d.x], 1);
        g_csr[p0] = s.x;
        int p1 = atomicAdd(&g_cur[d.y], 1);
        g_csr[p1] = s.y;
    }
}

// ---------------- mean aggregation: warp/node, bf16 gather, unroll 8 ---------
__global__ __launch_bounds__(256) void k_agg() {
    int node = (blockIdx.x * blockDim.x + threadIdx.x) >> 5;
    int lane = threadIdx.x & 31;
    if (node >= N_NODES) return;
    int s = g_off[node], e = g_off[node + 1];
    float ax = 0.f, ay = 0.f, az = 0.f, aw = 0.f;
    const uint2* base = (const uint2*)g_hb;
    int i = s;
    for (; i + 8 <= e; i += 8) {
        uint2 r[8];
#pragma unroll
        for (int q = 0; q < 8; q++)
            r[q] = __ldg(base + (size_t)__ldg(&g_csr[i + q]) * (FEAT / 4) + lane);
#pragma unroll
        for (int q = 0; q < 8; q++) {
            float f[4];
            bf4_to_f4(r[q], f);
            ax += f[0]; ay += f[1]; az += f[2]; aw += f[3];
        }
    }
    for (; i < e; i++) {
        uint2 r = __ldg(base + (size_t)__ldg(&g_csr[i]) * (FEAT / 4) + lane);
        float f[4];
        bf4_to_f4(r, f);
        ax += f[0]; ay += f[1]; az += f[2]; aw += f[3];
    }
    float inv = 1.0f / g_cnt[node];
    uint2 o;
    o.x = bf16pair(ax * inv, ay * inv);
    o.y = bf16pair(az * inv, aw * inv);
    *((uint2*)g_meanb + (size_t)node * (FEAT / 4) + lane) = o;
}

// ---------------- tensor-core fused GEMM, bf16 mma m16n8k16 ------------------
// g_hb <- relu(mean@W1 + h@W2 + bias)   (in place; always bf16 out)
#define GBM 128
#define GBK 32
#define APW 20
#define BPW 136
__global__ __launch_bounds__(256) void k_gemm_tc(
    const float* __restrict__ W1, const float* __restrict__ W2,
    const float* __restrict__ bias, int nrows)
{
    __shared__ unsigned As[GBM * APW];   // 10240 B
    __shared__ unsigned Bs[16 * BPW];    //  8704 B

    int row0 = blockIdx.x * GBM;
    int tid  = threadIdx.x;
    int lane = tid & 31;
    int wid  = tid >> 5;
    int wm   = wid & 3;
    int wn   = wid >> 2;

    int am  = tid >> 3;
    int aw2 = (tid & 7) * 2;
    int bn_s  = tid & 127;
    int bhalf = tid >> 7;

    uint2  ar[4];
    float2 wv[8];

    auto load_chunk = [&](int c) {
        int ph = c >> 2, k0 = (c & 3) * GBK;
        const uint2* __restrict__ Ab = ph ? (const uint2*)g_hb : (const uint2*)g_meanb;
        const float* __restrict__ W  = ph ? W2 : W1;
#pragma unroll
        for (int p = 0; p < 4; p++) {
            int grow = row0 + am + p * 32;
            ar[p] = (grow < nrows)
                ? __ldg(Ab + ((size_t)grow * FEAT + k0 + aw2 * 2) / 4)
                : make_uint2(0u, 0u);
        }
#pragma unroll
        for (int p = 0; p < 8; p++) {
            int kp = 2 * p + bhalf;
            wv[p].x = __ldg(&W[(size_t)(k0 + 2 * kp) * FEAT + bn_s]);
            wv[p].y = __ldg(&W[(size_t)(k0 + 2 * kp + 1) * FEAT + bn_s]);
        }
    };

    float d[2][8][4];
#pragma unroll
    for (int mt = 0; mt < 2; mt++)
#pragma unroll
        for (int nt = 0; nt < 8; nt++)
#pragma unroll
            for (int q = 0; q < 4; q++) d[mt][nt][q] = 0.0f;

    load_chunk(0);
    for (int c = 0; c < 8; c++) {
#pragma unroll
        for (int p = 0; p < 4; p++) {
            int row = am + p * 32;
            *(uint2*)&As[row * APW + aw2] = ar[p];
        }
#pragma unroll
        for (int p = 0; p < 8; p++) {
            int kp = 2 * p + bhalf;
            Bs[kp * BPW + bn_s] = bf16pair(wv[p].x, wv[p].y);
        }
        __syncthreads();
        if (c < 7) load_chunk(c + 1);

#pragma unroll
        for (int ks = 0; ks < 2; ks++) {
            unsigned a[2][4], b[8][2];
            int arow = wm * 32 + (lane >> 2);
            int ka   = ks * 8 + (lane & 3);
#pragma unroll
            for (int mt = 0; mt < 2; mt++) {
                int r0 = arow + mt * 16;
                a[mt][0] = As[r0 * APW + ka];
                a[mt][1] = As[(r0 + 8) * APW + ka];
                a[mt][2] = As[r0 * APW + ka + 4];
                a[mt][3] = As[(r0 + 8) * APW + ka + 4];
            }
            int kb  = ks * 8 + (lane & 3);
            int bn0 = wn * 64 + (lane >> 2);
#pragma unroll
            for (int nt = 0; nt < 8; nt++) {
                b[nt][0] = Bs[kb * BPW + bn0 + nt * 8];
                b[nt][1] = Bs[(kb + 4) * BPW + bn0 + nt * 8];
            }
#pragma unroll
            for (int mt = 0; mt < 2; mt++)
#pragma unroll
                for (int nt = 0; nt < 8; nt++)
                    mma_bf16(d[mt][nt], a[mt], b[nt]);
        }
        __syncthreads();
    }

    // ---- epilogue: bias + relu, bf16 ----
    int rbase = row0 + wm * 32 + (lane >> 2);
    int cbase = wn * 64 + (lane & 3) * 2;
#pragma unroll
    for (int nt = 0; nt < 8; nt++) {
        int col = cbase + nt * 8;
        float bv0 = __ldg(&bias[col]);
        float bv1 = __ldg(&bias[col + 1]);
#pragma unroll
        for (int mt = 0; mt < 2; mt++) {
#pragma unroll
            for (int half = 0; half < 2; half++) {
                int r = rbase + mt * 16 + half * 8;
                if (r < nrows) {
                    float ox = fmaxf(d[mt][nt][half * 2 + 0] + bv0, 0.0f);
                    float oy = fmaxf(d[mt][nt][half * 2 + 1] + bv1, 0.0f);
                    *(unsigned*)(g_hb + (size_t)r * FEAT + col) = bf16pair(ox, oy);
                }
            }
        }
    }
}

// ---------------- fused attention pooling + MLP head (1 block / graph) -------
// reads bf16 g_hb
__global__ __launch_bounds__(128) void k_attnpool(
    const float* __restrict__ gate_w, const float* __restrict__ gate_b,
    const float* __restrict__ lin1_w, const float* __restrict__ lin1_b,
    const float* __restrict__ lin2_w, const float* __restrict__ lin2_b,
    float* __restrict__ out)
{
    int g  = blockIdx.x;
    int lo = (g == 0) ? 0 : g_end[g - 1];
    int hi = g_end[g];
    int t = threadIdx.x, warp = t >> 5, lane = t & 31;

    __shared__ float red4[4];
    __shared__ float s_m, s_s;
    __shared__ float sp[FEAT];
    __shared__ float so[FEAT];
    __shared__ float lg[N_CLASSES];

    // ---- pass 1: gate per node + block max ----
    float4 wv = *(const float4*)(gate_w + lane * 4);
    float gb = __ldg(&gate_b[0]);
    float lmax = -1e30f;
    const uint2* hq = (const uint2*)g_hb;
    for (int node = lo + warp; node < hi; node += 4) {
        uint2 r = __ldg(hq + (size_t)node * (FEAT / 4) + lane);
        float f[4];
        bf4_to_f4(r, f);
        float s = f[0] * wv.x + f[1] * wv.y + f[2] * wv.z + f[3] * wv.w;
#pragma unroll
        for (int d = 16; d > 0; d >>= 1) s += __shfl_xor_sync(0xFFFFFFFFu, s, d);
        s += gb;
        if (lane == 0) g_gate[node] = s;
        lmax = fmaxf(lmax, s);
    }
    if (lane == 0) red4[warp] = lmax;
    __syncthreads();
    if (t == 0)
        s_m = fmaxf(fmaxf(red4[0], red4[1]), fmaxf(red4[2], red4[3]));
    __syncthreads();
    float m = s_m;

    // ---- pass 2: exp + sum ----
    float part = 0.0f;
    for (int node = lo + t; node < hi; node += 128) {
        float e = expf(g_gate[node] - m);
        g_gate[node] = e;
        part += e;
    }
#pragma unroll
    for (int d = 16; d > 0; d >>= 1) part += __shfl_xor_sync(0xFFFFFFFFu, part, d);
    if (lane == 0) red4[warp] = part;
    __syncthreads();
    if (t == 0) s_s = red4[0] + red4[1] + red4[2] + red4[3];
    __syncthreads();
    float s = s_s;
    float invs = (s > 0.0f) ? 1.0f / s : 0.0f;

    // ---- pass 3: weighted feature sum (thread t owns feature t) ----
    float acc = 0.0f;
#pragma unroll 4
    for (int node = lo; node < hi; node++)
        acc += g_gate[node] *
               __bfloat162float(g_hb[(size_t)node * FEAT + t]);
    sp[t] = acc * invs;
    __syncthreads();

    // ---- head: relu(lin1) -> lin2 -> log_softmax ----
    float h1 = lin1_b[t];
#pragma unroll 8
    for (int k = 0; k < FEAT; k++)
        h1 = fmaf(sp[k], lin1_w[(size_t)k * FEAT + t], h1);
    so[t] = fmaxf(h1, 0.0f);
    __syncthreads();

    if (t < N_CLASSES) {
        float a = lin2_b[t];
#pragma unroll 8
        for (int k = 0; k < FEAT; k++)
            a = fmaf(so[k], lin2_w[(size_t)k * N_CLASSES + t], a);
        lg[t] = a;
    }
    __syncthreads();

    if (t == 0) {
        float mx = lg[0];
#pragma unroll
        for (int j = 1; j < N_CLASSES; j++) mx = fmaxf(mx, lg[j]);
        float se = 0.0f;
#pragma unroll
        for (int j = 0; j < N_CLASSES; j++) se += expf(lg[j] - mx);
        float l = logf(se);
#pragma unroll
        for (int j = 0; j < N_CLASSES; j++)
            out[(size_t)g * N_CLASSES + j] = lg[j] - mx - l;
    }
}

// ---------------- launch ----------------
extern "C" void kernel_launch(void* const* d_in, const int* in_sizes, int n_in,
                              void* d_out, int out_size) {
    const float* x      = (const float*)d_in[0];
    const int*   ei     = (const int*)  d_in[1];
    const int*   batch  = (const int*)  d_in[2];
    const float* w1l = (const float*)d_in[3];
    const float* b1  = (const float*)d_in[4];
    const float* w1r = (const float*)d_in[5];
    const float* w2l = (const float*)d_in[6];
    const float* b2  = (const float*)d_in[7];
    const float* w2r = (const float*)d_in[8];
    const float* w3l = (const float*)d_in[9];
    const float* b3  = (const float*)d_in[10];
    const float* w3r = (const float*)d_in[11];
    const float* gate_w = (const float*)d_in[12];
    const float* gate_b = (const float*)d_in[13];
    const float* lin1_w = (const float*)d_in[14];
    const float* lin1_b = (const float*)d_in[15];
    const float* lin2_w = (const float*)d_in[16];
    const float* lin2_b = (const float*)d_in[17];
    float* out = (float*)d_out;

    const int TB = 256;

    k_setup<<<(N_NODES * FEAT / 4 + TB - 1) / TB, TB>>>(x, batch);
    k_hist<<<(N_EDGES / 2 + TB - 1) / TB, TB>>>(ei);
    k_scan_a<<<SCAN_NBLK, 256>>>();
    k_scan_b<<<1, 256>>>();
    k_scan_c<<<SCAN_NBLK, 256>>>();
    k_scatter<<<(N_EDGES / 2 + TB - 1) / TB, TB>>>(ei);

    int agg_blocks  = (N_NODES * 32 + TB - 1) / TB;
    int gemm_blocks = (N_NODES + GBM - 1) / GBM;

    // layer 1: shadow <- relu(mean(shadow)@w1l + shadow@w1r + b1)
    k_agg<<<agg_blocks, TB>>>();
    k_gemm_tc<<<gemm_blocks, 256>>>(w1l, w1r, b1, N_NODES);
    // layer 2
    k_agg<<<agg_blocks, TB>>>();
    k_gemm_tc<<<gemm_blocks, 256>>>(w2l, w2r, b2, N_NODES);
    // layer 3
    k_agg<<<agg_blocks, TB>>>();
    k_gemm_tc<<<gemm_blocks, 256>>>(w3l, w3r, b3, N_NODES);

    // fused attentional aggregation + head (bf16 h)
    k_attnpool<<<N_GRAPHS, 128>>>(gate_w, gate_b, lin1_w, lin1_b,
                                  lin2_w, lin2_b, out);
}